// round 8
// baseline (speedup 1.0000x reference)
#include <cuda_runtime.h>
#include <cuda_fp16.h>
#include <stdint.h>

#define P_PTS 200000
#define C_CH  32
#define N_B   4
#define K_FR  8
#define H_IMG 256
#define W_IMG 256
#define TILE  64          // pixels per block (one 64-wide strip)
#define TPR   (W_IMG / TILE)

// Transposed + fp16 point features: (P, C) half = 64B per point.
struct alignas(16) half8 { __half2 h0, h1, h2, h3; };
__device__ __half2 g_tab2[P_PTS * (C_CH / 2)];   // 12.8 MB

// ---------------------------------------------------------------------------
// Kernel 1: transpose + downconvert ptclds (C,P) f32 -> (P,C) f16.
// ---------------------------------------------------------------------------
__global__ void __launch_bounds__(256) transpose_kernel(const float* __restrict__ ptclds) {
    __shared__ float tile[32][33];
    const int p0  = blockIdx.x * 32;
    const int tid = threadIdx.x;
    const int col = tid & 31;
    const int r0  = tid >> 5;

#pragma unroll
    for (int i = 0; i < 4; i++) {
        const int c = r0 + i * 8;
        tile[c][col] = ptclds[c * P_PTS + p0 + col];   // coalesced 128B rows
    }
    __syncthreads();

    __half* __restrict__ gh = reinterpret_cast<__half*>(g_tab2);
#pragma unroll
    for (int i = 0; i < 4; i++) {
        const int idx = tid + i * 256;
        const int pl  = idx >> 5;
        const int c   = idx & 31;
        gh[(p0 + pl) * C_CH + c] = __float2half_rn(tile[c][pl]);
    }
}

// ---------------------------------------------------------------------------
// Kernel 2: composite. 256 threads = 8 warps covering a 64-pixel strip.
// Warp handles 8 pixels: lane>>2 = pixel, lane&2bits = channel-octet (16B).
// One LDG.128 gathers one k for 8 pixels -> per-pixel instruction cost halved
// vs R7 while keeping the 1-wavefront/pixel/k floor and MLP=8 per warp.
// ---------------------------------------------------------------------------
__global__ void __launch_bounds__(256) composite_kernel(
    const int*   __restrict__ frags,
    const float* __restrict__ alphas,
    float*       __restrict__ out)
{
    __shared__ int   s_frag[K_FR][TILE];
    __shared__ float s_alpha[K_FR][TILE];
    __shared__ float s_out[C_CH][TILE + 1];   // row stride 65 -> conflict-free

    const int b   = blockIdx.x;
    const int n   = b / (H_IMG * TPR);
    const int rem = b % (H_IMG * TPR);
    const int h   = rem / TPR;
    const int w0  = (rem % TPR) * TILE;

    const int tid = threadIdx.x;

    // Stage fragments + alphas: 512 elements each, 2 per thread, coalesced.
#pragma unroll
    for (int i = 0; i < 2; i++) {
        const int idx = tid + i * 256;
        const int k   = idx >> 6;          // 0..7
        const int wi  = idx & 63;          // 0..63
        const int base = ((n * K_FR + k) * H_IMG + h) * W_IMG + w0 + wi;
        s_frag[k][wi]  = frags[base];
        s_alpha[k][wi] = alphas[base];
    }
    __syncthreads();

    const int lane = tid & 31;
    const int wid  = tid >> 5;                // 0..7
    const int pi   = wid * 8 + (lane >> 2);   // pixel 0..63 within strip
    const int cq   = lane & 3;                // channel octet 0..3 (8 ch each)

    // Compositing weights (redundant across only 4 lanes per pixel).
    float wgt[K_FR];
    int   pofs[K_FR];
    float T = 1.0f;
#pragma unroll
    for (int kk = 0; kk < K_FR; kk++) {
        const int   p     = s_frag[kk][pi];
        const bool  valid = (p >= 0);
        const float a     = valid ? s_alpha[kk][pi] : 0.0f;
        wgt[kk]  = a * T;
        T       *= (1.0f - a);
        int pc   = valid ? p : 0;
        pc       = (pc < P_PTS) ? pc : (P_PTS - 1);   // safety clamp
        pofs[kk] = pc * (C_CH / 8) + cq;              // half8 (16B) offset
    }

    // 8 independent LDG.128 gathers (each covers 8 pixels) + fp32 FMA reduce.
    const half8* __restrict__ tab = reinterpret_cast<const half8*>(g_tab2);
    float acc[8];
#pragma unroll
    for (int j = 0; j < 8; j++) acc[j] = 0.0f;

#pragma unroll
    for (int kk = 0; kk < K_FR; kk++) {
        const half8  f  = tab[pofs[kk]];
        const float2 a0 = __half22float2(f.h0);
        const float2 a1 = __half22float2(f.h1);
        const float2 a2 = __half22float2(f.h2);
        const float2 a3 = __half22float2(f.h3);
        const float  w  = wgt[kk];
        acc[0] += w * a0.x;  acc[1] += w * a0.y;
        acc[2] += w * a1.x;  acc[3] += w * a1.y;
        acc[4] += w * a2.x;  acc[5] += w * a2.y;
        acc[6] += w * a3.x;  acc[7] += w * a3.y;
    }

    // Scatter: banks (8cq + j + pi) mod 32 distinct across each warp per j.
#pragma unroll
    for (int j = 0; j < 8; j++)
        s_out[cq * 8 + j][pi] = acc[j];
    __syncthreads();

    // Write out: 32 channels x 64 pixels; each warp writes contiguous 128B.
#pragma unroll
    for (int i = 0; i < 8; i++) {
        const int idx = tid + i * 256;
        const int c   = idx >> 6;          // 0..31
        const int pw  = idx & 63;          // 0..63
        out[((n * C_CH + c) * H_IMG + h) * W_IMG + w0 + pw] = s_out[c][pw];
    }
}

extern "C" void kernel_launch(void* const* d_in, const int* in_sizes, int n_in,
                              void* d_out, int out_size) {
    const int*   frags  = (const int*)d_in[0];    // int32 (N,K,H,W)
    const float* alphas = (const float*)d_in[1];  // f32   (N,K,H,W)
    const float* ptclds = (const float*)d_in[2];  // f32   (C,P)
    float*       out    = (float*)d_out;          // f32   (N,C,H,W)

    transpose_kernel<<<P_PTS / 32, 256>>>(ptclds);
    composite_kernel<<<N_B * H_IMG * TPR, 256>>>(frags, alphas, out);
}

// round 10
// speedup vs baseline: 1.0085x; 1.0085x over previous
#include <cuda_runtime.h>
#include <cuda_fp16.h>
#include <stdint.h>

#define P_PTS 200000
#define C_CH  32
#define N_B   4
#define K_FR  8
#define H_IMG 256
#define W_IMG 256
#define TILE  16                 // pixels per block
#define TPR   (W_IMG / TILE)     // 16 tiles per image row

// Transposed + fp16 point features: (P, C) half = 64B per point.
__device__ __half2 g_tab2[P_PTS * (C_CH / 2)];   // 12.8 MB

// ---------------------------------------------------------------------------
// Kernel 1: transpose + downconvert ptclds (C,P) f32 -> (P,C) f16.
// 64 points per block, float4 loads, half2 stores.
// ---------------------------------------------------------------------------
__global__ void __launch_bounds__(256) transpose_kernel(const float* __restrict__ ptclds) {
    __shared__ float tile[32][65];   // 32 channels x 64 points, padded
    const int p0  = blockIdx.x * 64;
    const int tid = threadIdx.x;

    // Load: each thread 8 floats (2x float4). c = tid>>3, col group = (tid&7)*8.
    {
        const int c   = tid >> 3;
        const int col = (tid & 7) * 8;
        const float4* src = reinterpret_cast<const float4*>(ptclds + c * P_PTS + p0 + col);
        const float4 v0 = src[0];
        const float4 v1 = src[1];
        tile[c][col + 0] = v0.x; tile[c][col + 1] = v0.y;
        tile[c][col + 2] = v0.z; tile[c][col + 3] = v0.w;
        tile[c][col + 4] = v1.x; tile[c][col + 5] = v1.y;
        tile[c][col + 6] = v1.z; tile[c][col + 7] = v1.w;
    }
    __syncthreads();

    // Store: 1024 half2 (64 points x 16 channel-pairs), 4 per thread, coalesced.
#pragma unroll
    for (int i = 0; i < 4; i++) {
        const int idx = tid + i * 256;
        const int pl  = idx >> 4;    // point within tile
        const int cp  = idx & 15;    // channel pair
        g_tab2[(p0 + pl) * (C_CH / 2) + cp] =
            __floats2half2_rn(tile[cp * 2][pl], tile[cp * 2 + 1][pl]);
    }
}

// ---------------------------------------------------------------------------
// Kernel 2: composite. 256 threads = 8 warps covering a 16-pixel strip.
// Warp handles 2 pixels: lane>>4 = pixel, lane&15 = channel-pair (half2).
// Each gather LDG.32 touches exactly 2 cache lines (one per pixel) ->
// minimal within-instruction wavefront replays (R8 lesson: 8 lines/instr bad).
// ---------------------------------------------------------------------------
__global__ void __launch_bounds__(256) composite_kernel(
    const int*   __restrict__ frags,
    const float* __restrict__ alphas,
    float*       __restrict__ out)
{
    __shared__ int2  s_fa[K_FR][TILE];        // packed (frag, alpha-bits)
    __shared__ float s_out[C_CH][TILE + 1];   // stride 17: conflict-free scatter

    const int b   = blockIdx.x;
    const int n   = b / (H_IMG * TPR);
    const int rem = b % (H_IMG * TPR);
    const int h   = rem / TPR;
    const int w0  = (rem % TPR) * TILE;

    const int tid = threadIdx.x;

    // Stage fragments + alphas packed: 128 elements, threads 0..127, coalesced.
    if (tid < K_FR * TILE) {
        const int k  = tid >> 4;
        const int wi = tid & 15;
        const int base = ((n * K_FR + k) * H_IMG + h) * W_IMG + w0 + wi;
        s_fa[k][wi] = make_int2(frags[base], __float_as_int(alphas[base]));
    }
    __syncthreads();

    const int lane = tid & 31;
    const int wid  = tid >> 5;                // 0..7
    const int pi   = wid * 2 + (lane >> 4);   // pixel 0..15 within strip
    const int cp   = lane & 15;               // channel pair 0..15

    // Compositing weights (one LDS.64 broadcast per k).
    float wgt[K_FR];
    int   pofs[K_FR];
    float T = 1.0f;
#pragma unroll
    for (int kk = 0; kk < K_FR; kk++) {
        const int2  fa    = s_fa[kk][pi];
        const int   p     = fa.x;
        const bool  valid = (p >= 0);
        const float a     = valid ? __int_as_float(fa.y) : 0.0f;
        wgt[kk]  = a * T;
        T       *= (1.0f - a);
        int pc   = valid ? p : 0;
        pc       = (pc < P_PTS) ? pc : (P_PTS - 1);   // safety clamp
        pofs[kk] = pc * (C_CH / 2) + cp;              // half2 offset
    }

    // 8 independent LDG.32 gathers (2 lines each) + fp32 FMA reduce.
    float2 acc = make_float2(0.0f, 0.0f);
#pragma unroll
    for (int kk = 0; kk < K_FR; kk++) {
        const float2 f = __half22float2(g_tab2[pofs[kk]]);
        const float  w = wgt[kk];
        acc.x += w * f.x;
        acc.y += w * f.y;
    }

    // Scatter: banks (2cp + j + pi) mod 32 distinct across each warp per j.
    s_out[cp * 2 + 0][pi] = acc.x;
    s_out[cp * 2 + 1][pi] = acc.y;
    __syncthreads();

    // Write out: 32 channels x 16 pixels; 64B coalesced segments per channel.
#pragma unroll
    for (int i = 0; i < 2; i++) {
        const int idx = tid + i * 256;
        const int c   = idx >> 4;          // 0..31
        const int pw  = idx & 15;          // 0..15
        out[((n * C_CH + c) * H_IMG + h) * W_IMG + w0 + pw] = s_out[c][pw];
    }
}

extern "C" void kernel_launch(void* const* d_in, const int* in_sizes, int n_in,
                              void* d_out, int out_size) {
    const int*   frags  = (const int*)d_in[0];    // int32 (N,K,H,W)
    const float* alphas = (const float*)d_in[1];  // f32   (N,K,H,W)
    const float* ptclds = (const float*)d_in[2];  // f32   (C,P)
    float*       out    = (float*)d_out;          // f32   (N,C,H,W)

    transpose_kernel<<<P_PTS / 64, 256>>>(ptclds);
    composite_kernel<<<N_B * H_IMG * TPR, 256>>>(frags, alphas, out);
}

// round 12
// speedup vs baseline: 1.3350x; 1.3238x over previous
#include <cuda_runtime.h>
#include <cuda_fp16.h>
#include <stdint.h>

#define P_PTS 200000
#define C_CH  32
#define N_B   4
#define K_FR  8
#define H_IMG 256
#define W_IMG 256
#define TILE  32                 // pixels per block
#define TPR   (W_IMG / TILE)     // 8 tiles per image row

// Transposed + fp16 point features: (P, C) half = 64B per point.
struct alignas(8) half4 { __half2 a, b; };
__device__ __half2 g_tab2[P_PTS * (C_CH / 2)];   // 12.8 MB

// ---------------------------------------------------------------------------
// Kernel 1: transpose + downconvert ptclds (C,P) f32 -> (P,C) f16.
// 64 points per block, float4 loads, half2 stores (measured ~6.1us in R10).
// ---------------------------------------------------------------------------
__global__ void __launch_bounds__(256) transpose_kernel(const float* __restrict__ ptclds) {
    __shared__ float tile[32][65];   // 32 channels x 64 points, padded
    const int p0  = blockIdx.x * 64;
    const int tid = threadIdx.x;

    {
        const int c   = tid >> 3;
        const int col = (tid & 7) * 8;
        const float4* src = reinterpret_cast<const float4*>(ptclds + c * P_PTS + p0 + col);
        const float4 v0 = src[0];
        const float4 v1 = src[1];
        tile[c][col + 0] = v0.x; tile[c][col + 1] = v0.y;
        tile[c][col + 2] = v0.z; tile[c][col + 3] = v0.w;
        tile[c][col + 4] = v1.x; tile[c][col + 5] = v1.y;
        tile[c][col + 6] = v1.z; tile[c][col + 7] = v1.w;
    }
    __syncthreads();

#pragma unroll
    for (int i = 0; i < 4; i++) {
        const int idx = tid + i * 256;
        const int pl  = idx >> 4;    // point within tile
        const int cp  = idx & 15;    // channel pair
        g_tab2[(p0 + pl) * (C_CH / 2) + cp] =
            __floats2half2_rn(tile[cp * 2][pl], tile[cp * 2 + 1][pl]);
    }
}

// ---------------------------------------------------------------------------
// Kernel 2: composite — R7's measured-best shape (4 px/warp, LDG.64 gather,
// 4 lines/instr) with ONE change: frag+alpha staged packed (int2) so the
// weight loop issues 8 LDS.64 instead of 16 LDS.32.
// ---------------------------------------------------------------------------
__global__ void __launch_bounds__(256) composite_kernel(
    const int*   __restrict__ frags,
    const float* __restrict__ alphas,
    float*       __restrict__ out)
{
    __shared__ int2  s_fa[K_FR][TILE];        // packed (frag, alpha-bits)
    __shared__ float s_out[C_CH][TILE + 1];   // stride 33: conflict-free

    const int b   = blockIdx.x;
    const int n   = b / (H_IMG * TPR);
    const int rem = b % (H_IMG * TPR);
    const int h   = rem / TPR;
    const int w0  = (rem % TPR) * TILE;

    const int tid = threadIdx.x;

    // Stage packed fragments + alphas: 256 pairs, one per thread, coalesced.
    {
        const int k  = tid >> 5;
        const int wi = tid & 31;
        const int base = ((n * K_FR + k) * H_IMG + h) * W_IMG + w0 + wi;
        s_fa[k][wi] = make_int2(frags[base], __float_as_int(alphas[base]));
    }
    __syncthreads();

    const int lane = tid & 31;
    const int wid  = tid >> 5;               // warp id 0..7
    const int pi   = wid * 4 + (lane >> 3);  // pixel within 32-pixel tile
    const int cq   = lane & 7;               // channel quad 0..7

    // Compositing weights: one LDS.64 per k (8 total).
    float wgt[K_FR];
    int   pofs[K_FR];
    float T = 1.0f;
#pragma unroll
    for (int kk = 0; kk < K_FR; kk++) {
        const int2  fa    = s_fa[kk][pi];
        const int   p     = fa.x;
        const bool  valid = (p >= 0);
        const float a     = valid ? __int_as_float(fa.y) : 0.0f;
        wgt[kk]  = a * T;
        T       *= (1.0f - a);
        int pc   = valid ? p : 0;
        pc       = (pc < P_PTS) ? pc : (P_PTS - 1);   // safety clamp
        pofs[kk] = pc * (C_CH / 4) + cq;              // half4 (8B) offset
    }

    // 8 independent LDG.64 gathers (4 lines/instr) + fp32 FMA reduce.
    const half4* __restrict__ tab = reinterpret_cast<const half4*>(g_tab2);
    float4 acc = make_float4(0.0f, 0.0f, 0.0f, 0.0f);
#pragma unroll
    for (int kk = 0; kk < K_FR; kk++) {
        const half4  f   = tab[pofs[kk]];
        const float2 f01 = __half22float2(f.a);
        const float2 f23 = __half22float2(f.b);
        const float  w   = wgt[kk];
        acc.x += w * f01.x;
        acc.y += w * f01.y;
        acc.z += w * f23.x;
        acc.w += w * f23.y;
    }

    // Scatter: banks (4cq + j + pi) mod 32 distinct per warp -> conflict-free.
    s_out[cq * 4 + 0][pi] = acc.x;
    s_out[cq * 4 + 1][pi] = acc.y;
    s_out[cq * 4 + 2][pi] = acc.z;
    s_out[cq * 4 + 3][pi] = acc.w;
    __syncthreads();

    // Write out: 32 channels x 32 pixels; each warp writes contiguous 128B.
#pragma unroll
    for (int i = 0; i < 4; i++) {
        const int idx = tid + i * 256;
        const int c   = idx >> 5;
        const int pw  = idx & 31;
        out[((n * C_CH + c) * H_IMG + h) * W_IMG + w0 + pw] = s_out[c][pw];
    }
}

extern "C" void kernel_launch(void* const* d_in, const int* in_sizes, int n_in,
                              void* d_out, int out_size) {
    const int*   frags  = (const int*)d_in[0];    // int32 (N,K,H,W)
    const float* alphas = (const float*)d_in[1];  // f32   (N,K,H,W)
    const float* ptclds = (const float*)d_in[2];  // f32   (C,P)
    float*       out    = (float*)d_out;          // f32   (N,C,H,W)

    transpose_kernel<<<P_PTS / 64, 256>>>(ptclds);
    composite_kernel<<<N_B * H_IMG * TPR, 256>>>(frags, alphas, out);
}

// round 14
// speedup vs baseline: 1.4287x; 1.0702x over previous
#include <cuda_runtime.h>
#include <cuda_fp16.h>
#include <stdint.h>

#define P_PTS 200000
#define C_CH  32
#define N_B   4
#define K_FR  8
#define H_IMG 256
#define W_IMG 256
#define TILE  32                 // pixels per block
#define TPR   (W_IMG / TILE)     // 8 tiles per image row

// Transposed + fp16 point features: (P, C) half = 64B per point.
__device__ __half2 g_tab2[P_PTS * (C_CH / 2)];   // 12.8 MB

// ---------------------------------------------------------------------------
// Kernel 1: transpose + downconvert ptclds (C,P) f32 -> (P,C) f16.
// 64 points per block, float4 loads, half2 stores (~5.8us, near DRAM-bound).
// ---------------------------------------------------------------------------
__global__ void __launch_bounds__(256) transpose_kernel(const float* __restrict__ ptclds) {
    __shared__ float tile[32][65];   // 32 channels x 64 points, padded
    const int p0  = blockIdx.x * 64;
    const int tid = threadIdx.x;

    {
        const int c   = tid >> 3;
        const int col = (tid & 7) * 8;
        const float4* src = reinterpret_cast<const float4*>(ptclds + c * P_PTS + p0 + col);
        const float4 v0 = src[0];
        const float4 v1 = src[1];
        tile[c][col + 0] = v0.x; tile[c][col + 1] = v0.y;
        tile[c][col + 2] = v0.z; tile[c][col + 3] = v0.w;
        tile[c][col + 4] = v1.x; tile[c][col + 5] = v1.y;
        tile[c][col + 6] = v1.z; tile[c][col + 7] = v1.w;
    }
    __syncthreads();

#pragma unroll
    for (int i = 0; i < 4; i++) {
        const int idx = tid + i * 256;
        const int pl  = idx >> 4;    // point within tile
        const int cp  = idx & 15;    // channel pair
        g_tab2[(p0 + pl) * (C_CH / 2) + cp] =
            __floats2half2_rn(tile[cp * 2][pl], tile[cp * 2 + 1][pl]);
    }
}

// ---------------------------------------------------------------------------
// Kernel 2: composite — R12 structure (4 px/warp, LDG.64 gather, packed int2
// weights) with L1-bypass cache hints:
//   gather  -> __ldcg (L2-resident table, ~2% L1 hit rate: skip L1 allocate)
//   staging -> __ldcs (one-shot streaming data)
// ---------------------------------------------------------------------------
__global__ void __launch_bounds__(256) composite_kernel(
    const int*   __restrict__ frags,
    const float* __restrict__ alphas,
    float*       __restrict__ out)
{
    __shared__ int2  s_fa[K_FR][TILE];        // packed (frag, alpha-bits)
    __shared__ float s_out[C_CH][TILE + 1];   // stride 33: conflict-free

    const int b   = blockIdx.x;
    const int n   = b / (H_IMG * TPR);
    const int rem = b % (H_IMG * TPR);
    const int h   = rem / TPR;
    const int w0  = (rem % TPR) * TILE;

    const int tid = threadIdx.x;

    // Stage packed fragments + alphas: 256 pairs, one per thread, coalesced.
    {
        const int k  = tid >> 5;
        const int wi = tid & 31;
        const int base = ((n * K_FR + k) * H_IMG + h) * W_IMG + w0 + wi;
        s_fa[k][wi] = make_int2(__ldcs(frags + base),
                                __float_as_int(__ldcs(alphas + base)));
    }
    __syncthreads();

    const int lane = tid & 31;
    const int wid  = tid >> 5;               // warp id 0..7
    const int pi   = wid * 4 + (lane >> 3);  // pixel within 32-pixel tile
    const int cq   = lane & 7;               // channel quad 0..7

    // Compositing weights: one LDS.64 per k (8 total).
    float wgt[K_FR];
    int   pofs[K_FR];
    float T = 1.0f;
#pragma unroll
    for (int kk = 0; kk < K_FR; kk++) {
        const int2  fa    = s_fa[kk][pi];
        const int   p     = fa.x;
        const bool  valid = (p >= 0);
        const float a     = valid ? __int_as_float(fa.y) : 0.0f;
        wgt[kk]  = a * T;
        T       *= (1.0f - a);
        int pc   = valid ? p : 0;
        pc       = (pc < P_PTS) ? pc : (P_PTS - 1);   // safety clamp
        pofs[kk] = pc * (C_CH / 4) + cq;              // 8B-quad offset
    }

    // 8 independent L1-bypassed LDG.64 gathers (4 lines/instr) + fp32 FMA.
    const uint2* __restrict__ tab = reinterpret_cast<const uint2*>(g_tab2);
    float4 acc = make_float4(0.0f, 0.0f, 0.0f, 0.0f);
#pragma unroll
    for (int kk = 0; kk < K_FR; kk++) {
        const uint2  raw = __ldcg(tab + pofs[kk]);
        const float2 f01 = __half22float2(*reinterpret_cast<const __half2*>(&raw.x));
        const float2 f23 = __half22float2(*reinterpret_cast<const __half2*>(&raw.y));
        const float  w   = wgt[kk];
        acc.x += w * f01.x;
        acc.y += w * f01.y;
        acc.z += w * f23.x;
        acc.w += w * f23.y;
    }

    // Scatter: banks (4cq + j + pi) mod 32 distinct per warp -> conflict-free.
    s_out[cq * 4 + 0][pi] = acc.x;
    s_out[cq * 4 + 1][pi] = acc.y;
    s_out[cq * 4 + 2][pi] = acc.z;
    s_out[cq * 4 + 3][pi] = acc.w;
    __syncthreads();

    // Write out: 32 channels x 32 pixels; each warp writes contiguous 128B.
#pragma unroll
    for (int i = 0; i < 4; i++) {
        const int idx = tid + i * 256;
        const int c   = idx >> 5;
        const int pw  = idx & 31;
        out[((n * C_CH + c) * H_IMG + h) * W_IMG + w0 + pw] = s_out[c][pw];
    }
}

extern "C" void kernel_launch(void* const* d_in, const int* in_sizes, int n_in,
                              void* d_out, int out_size) {
    const int*   frags  = (const int*)d_in[0];    // int32 (N,K,H,W)
    const float* alphas = (const float*)d_in[1];  // f32   (N,K,H,W)
    const float* ptclds = (const float*)d_in[2];  // f32   (C,P)
    float*       out    = (float*)d_out;          // f32   (N,C,H,W)

    transpose_kernel<<<P_PTS / 64, 256>>>(ptclds);
    composite_kernel<<<N_B * H_IMG * TPR, 256>>>(frags, alphas, out);
}

// round 15
// speedup vs baseline: 1.5366x; 1.0755x over previous
#include <cuda_runtime.h>
#include <cuda_fp16.h>
#include <stdint.h>

#define P_PTS 200000
#define C_CH  32
#define N_B   4
#define K_FR  8
#define H_IMG 256
#define W_IMG 256
#define TILE  32                 // pixels per block
#define TPR   (W_IMG / TILE)     // 8 tiles per image row

// Transposed + fp16 point features: (P, C) half = 64B per point.
__device__ __half2 g_tab2[P_PTS * (C_CH / 2)];   // 12.8 MB

// ---------------------------------------------------------------------------
// Kernel 1: transpose + downconvert ptclds (C,P) f32 -> (P,C) f16.
// 64 points per block, float4 loads, half2 stores (~5.8us, near DRAM-bound).
// ---------------------------------------------------------------------------
__global__ void __launch_bounds__(256) transpose_kernel(const float* __restrict__ ptclds) {
    __shared__ float tile[32][65];   // 32 channels x 64 points, padded
    const int p0  = blockIdx.x * 64;
    const int tid = threadIdx.x;

    {
        const int c   = tid >> 3;
        const int col = (tid & 7) * 8;
        const float4* src = reinterpret_cast<const float4*>(ptclds + c * P_PTS + p0 + col);
        const float4 v0 = src[0];
        const float4 v1 = src[1];
        tile[c][col + 0] = v0.x; tile[c][col + 1] = v0.y;
        tile[c][col + 2] = v0.z; tile[c][col + 3] = v0.w;
        tile[c][col + 4] = v1.x; tile[c][col + 5] = v1.y;
        tile[c][col + 6] = v1.z; tile[c][col + 7] = v1.w;
    }
    __syncthreads();

#pragma unroll
    for (int i = 0; i < 4; i++) {
        const int idx = tid + i * 256;
        const int pl  = idx >> 4;    // point within tile
        const int cp  = idx & 15;    // channel pair
        g_tab2[(p0 + pl) * (C_CH / 2) + cp] =
            __floats2half2_rn(tile[cp * 2][pl], tile[cp * 2 + 1][pl]);
    }
}

// ---------------------------------------------------------------------------
// Kernel 2: composite. R14 was issue-bound (66%) with 8-way-redundant weight
// math. Now warp 0 precomputes per-pixel (weight, table-offset) pairs ONCE
// (loading frag/alpha coalesced straight from gmem — staging smem removed),
// and the gather loop shrinks to LDS.64 + IADD + LDG.64(cg) + cvt + 4 FFMA
// per k. Gather shape stays at the measured-best 4 px/warp, 4 lines/instr.
// ---------------------------------------------------------------------------
__global__ void __launch_bounds__(256) composite_kernel(
    const int*   __restrict__ frags,
    const float* __restrict__ alphas,
    float*       __restrict__ out)
{
    __shared__ int2  s_wp[K_FR][TILE];        // packed (wgt bits, pc*8)
    __shared__ float s_out[C_CH][TILE + 1];   // stride 33: conflict-free

    const int b   = blockIdx.x;
    const int n   = b / (H_IMG * TPR);
    const int rem = b % (H_IMG * TPR);
    const int h   = rem / TPR;
    const int w0  = (rem % TPR) * TILE;

    const int tid = threadIdx.x;

    // Phase 1: warp 0 computes weights+offsets, one thread per pixel.
    // Per k the 32 lanes read 32 consecutive frags/alphas -> coalesced.
    if (tid < TILE) {
        const int pbase = ((n * K_FR) * H_IMG + h) * W_IMG + w0 + tid;
        float T = 1.0f;
#pragma unroll
        for (int kk = 0; kk < K_FR; kk++) {
            const int   off   = pbase + kk * (H_IMG * W_IMG);
            const int   p     = __ldcs(frags + off);
            const float araw  = __ldcs(alphas + off);
            const bool  valid = (p >= 0);
            const float a     = valid ? araw : 0.0f;
            const float w     = a * T;
            T *= (1.0f - a);
            int pc = valid ? p : 0;
            pc     = (pc < P_PTS) ? pc : (P_PTS - 1);   // safety clamp
            s_wp[kk][tid] = make_int2(__float_as_int(w), pc * (C_CH / 4));
        }
    }
    __syncthreads();

    const int lane = tid & 31;
    const int wid  = tid >> 5;               // warp id 0..7
    const int pi   = wid * 4 + (lane >> 3);  // pixel within 32-pixel tile
    const int cq   = lane & 7;               // channel quad 0..7

    // Phase 2: 8 independent L1-bypassed LDG.64 gathers + fp32 FMA reduce.
    const uint2* __restrict__ tab = reinterpret_cast<const uint2*>(g_tab2);
    float4 acc = make_float4(0.0f, 0.0f, 0.0f, 0.0f);
#pragma unroll
    for (int kk = 0; kk < K_FR; kk++) {
        const int2   wp  = s_wp[kk][pi];          // broadcast LDS.64
        const uint2  raw = __ldcg(tab + wp.y + cq);
        const float  w   = __int_as_float(wp.x);
        const float2 f01 = __half22float2(*reinterpret_cast<const __half2*>(&raw.x));
        const float2 f23 = __half22float2(*reinterpret_cast<const __half2*>(&raw.y));
        acc.x += w * f01.x;
        acc.y += w * f01.y;
        acc.z += w * f23.x;
        acc.w += w * f23.y;
    }

    // Scatter: banks (4cq + j + pi) mod 32 distinct per warp -> conflict-free.
    s_out[cq * 4 + 0][pi] = acc.x;
    s_out[cq * 4 + 1][pi] = acc.y;
    s_out[cq * 4 + 2][pi] = acc.z;
    s_out[cq * 4 + 3][pi] = acc.w;
    __syncthreads();

    // Epilogue: 32 channels x 32 pixels; each warp stores contiguous 128B.
    // .cs hint: streaming output must not evict the L2-resident table.
#pragma unroll
    for (int i = 0; i < 4; i++) {
        const int idx = tid + i * 256;
        const int c   = idx >> 5;
        const int pw  = idx & 31;
        __stcs(&out[((n * C_CH + c) * H_IMG + h) * W_IMG + w0 + pw], s_out[c][pw]);
    }
}

extern "C" void kernel_launch(void* const* d_in, const int* in_sizes, int n_in,
                              void* d_out, int out_size) {
    const int*   frags  = (const int*)d_in[0];    // int32 (N,K,H,W)
    const float* alphas = (const float*)d_in[1];  // f32   (N,K,H,W)
    const float* ptclds = (const float*)d_in[2];  // f32   (C,P)
    float*       out    = (float*)d_out;          // f32   (N,C,H,W)

    transpose_kernel<<<P_PTS / 64, 256>>>(ptclds);
    composite_kernel<<<N_B * H_IMG * TPR, 256>>>(frags, alphas, out);
}